// round 15
// baseline (speedup 1.0000x reference)
#include <cuda_runtime.h>
#include <cuda_fp16.h>
#include <math.h>

#define B_  512
#define R_  1152
#define C_  8
#define J_  10
#define O_  16
#define JO_ 160

// Scratch (device globals: no allocations allowed in kernel_launch)
// u_hat stored fp16, packed across batch pairs: g_U16[p, r, jo] = (u[2p], u[2p+1])
__device__ __half2 g_U16[(size_t)(B_ / 2) * R_ * JO_];   // 188 MB
__device__ float   g_S[3][B_ * JO_];                     // s accumulators
__device__ float   g_V0[B_ * JO_];                       // v0
__device__ float   g_VSUM[B_ * JO_];                     // v0 + v1

__device__ __forceinline__ __half2 h2exp2_(__half2 x) {
    unsigned r, xi = *reinterpret_cast<unsigned*>(&x);
    asm("ex2.approx.f16x2 %0, %1;" : "=r"(r) : "r"(xi));
    return *reinterpret_cast<__half2*>(&r);
}

// ---------------------------------------------------------------------------
__global__ void k_zero() {
    int i = blockIdx.x * blockDim.x + threadIdx.x;
    if (i < 3 * B_ * JO_) ((float*)g_S)[i] = 0.0f;
}

// ---------------------------------------------------------------------------
// u_hat kernel — R12 compute shape, 128-thread blocks (v8): at ~96 regs the
// 128-thr granularity yields 5 blocks x 4 warps = 20 warps/SM (was 2x8=16).
// Each warp owns (8 batches = 4 pairs, 8-r slice); W staged once in smem.
__global__ void __launch_bounds__(128) k_uhat(const float* __restrict__ x,
                                              const float* __restrict__ W) {
    __shared__ float4 s_w[8 * 320];        // 8 r x 320 float4 = 40KB, swizzled
    const int tid  = threadIdx.x;
    const int lane = tid & 31;
    const int warp = tid >> 5;             // 0..3
    const int sl   = blockIdx.x % 144;     // 144 slices of 8 r
    const int bg   = blockIdx.x / 144;     // 16 groups of 32 b
    const int r0   = sl * 8;
    const int b0   = bg * 32 + warp * 8;   // this warp's 8 batches

    {
        const float4* Wg = (const float4*)(W + (size_t)r0 * 1280);
        for (int i = tid; i < 8 * 320; i += 128) {
            int r  = i / 320;
            int f  = i - r * 320;
            int jo = f >> 1, ch = f & 1;
            int k  = jo >> 5, l = jo & 31;
            s_w[r * 320 + (k * 2 + ch) * 32 + l] = Wg[r * 320 + f];
        }
    }
    __syncthreads();

    __half2 sacc2[4][5];
    #pragma unroll
    for (int pp = 0; pp < 4; pp++)
        #pragma unroll
        for (int k = 0; k < 5; k++) sacc2[pp][k] = __floats2half2_rn(0.f, 0.f);

    #pragma unroll
    for (int rq = 0; rq < 2; rq++) {
        const int rbase = r0 + rq * 4;

        float xq[8];
        #pragma unroll
        for (int bb = 0; bb < 8; bb++)
            xq[bb] = x[(size_t)(b0 + bb) * (R_ * C_) + (size_t)rbase * C_ + lane];

        #pragma unroll
        for (int rr = 0; rr < 4; rr++) {
            const int rloc = rq * 4 + rr;
            const int r    = rbase + rr;

            const float4* wrow = s_w + rloc * 320;
            float4 wa[5], wb[5];
            #pragma unroll
            for (int k = 0; k < 5; k++) {
                wa[k] = wrow[(2 * k)     * 32 + lane];
                wb[k] = wrow[(2 * k + 1) * 32 + lane];
            }

            float uhold[5];
            #pragma unroll
            for (int bb = 0; bb < 8; bb++) {
                float xc[8];
                #pragma unroll
                for (int c = 0; c < 8; c++)
                    xc[c] = __shfl_sync(0xffffffffu, xq[bb], rr * 8 + c);

                float u[5];
                #pragma unroll
                for (int k = 0; k < 5; k++) {
                    float t = wa[k].x * xc[0];
                    t = fmaf(wa[k].y, xc[1], t);
                    t = fmaf(wa[k].z, xc[2], t);
                    t = fmaf(wa[k].w, xc[3], t);
                    t = fmaf(wb[k].x, xc[4], t);
                    t = fmaf(wb[k].y, xc[5], t);
                    t = fmaf(wb[k].z, xc[6], t);
                    t = fmaf(wb[k].w, xc[7], t);
                    u[k] = t;
                }

                if (bb & 1) {
                    const int pp = bb >> 1;
                    __half2* up = g_U16 +
                        ((size_t)((b0 >> 1) + pp) * R_ + r) * JO_ + lane;
                    #pragma unroll
                    for (int k = 0; k < 5; k++) {
                        __half2 h = __floats2half2_rn(uhold[k], u[k]);
                        up[32 * k] = h;
                        sacc2[pp][k] = __hadd2(sacc2[pp][k], h);
                    }
                } else {
                    #pragma unroll
                    for (int k = 0; k < 5; k++) uhold[k] = u[k];
                }
            }
        }
    }

    #pragma unroll
    for (int pp = 0; pp < 4; pp++)
        #pragma unroll
        for (int k = 0; k < 5; k++) {
            float2 s = __half22float2(sacc2[pp][k]);
            int jo = lane + 32 * k;
            atomicAdd(&g_S[0][(b0 + 2 * pp)     * JO_ + jo], s.x);
            atomicAdd(&g_S[0][(b0 + 2 * pp + 1) * JO_ + jo], s.y);
        }
}

// ---------------------------------------------------------------------------
// Routing iteration v7 — R14's in-thread o-reduction with its occupancy
// problem fixed. Same math: lane = (rr = lane>>4, j = lane&15, act j<10),
// in-thread dot (4 LDG.128 + 16 HFMA2, no o-shuffles), softmax over j via
// 16-lane butterflies, fp16 fine (4-r windows) -> fp16 coarse.
// Occupancy fixes vs R14 (occ was 35.8%, regs 70, smem 21KB):
//  - 128-thread blocks, __launch_bounds__(128,8): 8 blocks x 4 warps =
//    32 warps/SM; 64-reg cap (body ~62 with v kept in smem, not hoisted).
//  - v read from smem IN-LOOP (4 LDS.128/step) instead of 16 hoisted regs.
//  - rr halves merged by one 16-SHFL pass before the epilogue -> ONE fp32
//    region per warp: smem 4*320*4B = 5.1KB (was 20.5KB).
__global__ void __launch_bounds__(128, 8) k_route(int vsel, int ssel) {
    __shared__ float   s_priv[4 * 320];    // [warp][bb*160 + o*10 + j]
    __shared__ __half2 v_s[10 * 20];       // padded: v_s[j*20+o]
    const int tid  = threadIdx.x;
    const int lane = tid & 31;
    const int w    = tid >> 5;             // 0..3
    const int p    = blockIdx.x / 24;      // 256 pairs x 24 blocks
    const int g    = blockIdx.x - p * 24;
    const int slice = g * 4 + w;           // 0..95, 12 r each
    const int r0   = slice * 12;
    const int rr   = lane >> 4;
    const int j    = lane & 15;
    const bool act = (j < 10);
    const int jc   = act ? j : 0;          // clamped for unguarded smem reads
    const int b0   = 2 * p;

    const float* __restrict__ V = vsel ? g_VSUM : g_V0;
    const float LOG2E = 1.4426950408889634f;

    // stage v (block-uniform): v_s[j*20+o] = (V[b0,j,o], V[b1,j,o]) * log2e
    for (int t = tid; t < 160; t += 128) {
        int jj = t >> 4, oo = t & 15;
        v_s[jj * 20 + oo] = __floats2half2_rn(V[b0 * JO_ + t] * LOG2E,
                                              V[(b0 + 1) * JO_ + t] * LOG2E);
    }
    __syncthreads();

    const __half2 HZERO = __floats2half2_rn(0.f, 0.f);
    const __half2 NEG   = __floats2half2_rn(-60000.f, -60000.f);
    __half2 fine[16], coarse[16];
    #pragma unroll
    for (int o = 0; o < 16; o++) { fine[o] = HZERO; coarse[o] = HZERO; }

    const __half2* __restrict__ ubase =
        g_U16 + ((size_t)p * R_ + r0 + rr) * JO_ + jc * 16;
    const uint4* vp4 = (const uint4*)(v_s + jc * 20);  // in-bounds for all lanes

    for (int step = 0; step < 6; step++) {
        // load u[r, j, 0..15] (b-paired half2) — 4x LDG.128, active lanes only
        __half2 u2[16];
        if (act) {
            const uint4* up4 =
                (const uint4*)(ubase + (size_t)(2 * step) * JO_);
            #pragma unroll
            for (int q = 0; q < 4; q++) {
                uint4 t = up4[q];
                u2[q * 4 + 0] = *(__half2*)&t.x;
                u2[q * 4 + 1] = *(__half2*)&t.y;
                u2[q * 4 + 2] = *(__half2*)&t.z;
                u2[q * 4 + 3] = *(__half2*)&t.w;
            }
        } else {
            #pragma unroll
            for (int o = 0; o < 16; o++) u2[o] = HZERO;
        }

        // in-thread dot over o (two chains for ILP); v from smem each step
        __half2 aA = HZERO, aB = HZERO;
        #pragma unroll
        for (int q = 0; q < 4; q++) {
            uint4 vq = vp4[q];
            aA = __hfma2(u2[q * 4 + 0], *(__half2*)&vq.x, aA);
            aB = __hfma2(u2[q * 4 + 1], *(__half2*)&vq.y, aB);
            aA = __hfma2(u2[q * 4 + 2], *(__half2*)&vq.z, aA);
            aB = __hfma2(u2[q * 4 + 3], *(__half2*)&vq.w, aB);
        }
        __half2 a2 = __hadd2(aA, aB);
        if (!act) a2 = NEG;                 // idle lanes neutral

        // softmax over j within each 16-lane half (4+4 SHFL total)
        __half2 m2 = a2;
        #pragma unroll
        for (int d = 1; d < 16; d <<= 1)
            m2 = __hmax2(m2, __shfl_xor_sync(0xffffffffu, m2, d));
        __half2 e2 = h2exp2_(__hsub2(a2, m2));
        __half2 z2 = e2;
        #pragma unroll
        for (int d = 1; d < 16; d <<= 1)
            z2 = __hadd2(z2, __shfl_xor_sync(0xffffffffu, z2, d));
        __half2 c2 = __hmul2(e2, h2rcp(z2));

        // accumulate c*u (idle lanes accumulate zeros — never stored)
        #pragma unroll
        for (int o = 0; o < 16; o++)
            fine[o] = __hfma2(c2, u2[o], fine[o]);

        if (step & 1) {                     // fold 4-r window into coarse
            #pragma unroll
            for (int o = 0; o < 16; o++) {
                coarse[o] = __hadd2(coarse[o], fine[o]);
                fine[o] = HZERO;
            }
        }
    }

    // merge rr halves: lanes (0,j) and (16,j) hold same (b,o,j) coordinates
    #pragma unroll
    for (int o = 0; o < 16; o++)
        coarse[o] = __hadd2(coarse[o],
                            __shfl_xor_sync(0xffffffffu, coarse[o], 16));

    // per-warp epilogue: one fp32 region per warp (plain STS, no atomics)
    if (act && rr == 0) {
        float* regn = s_priv + w * 320;
        #pragma unroll
        for (int o = 0; o < 16; o++) {
            float2 f = __half22float2(coarse[o]);
            regn[      o * 10 + j] = f.x;
            regn[160 + o * 10 + j] = f.y;
        }
    }
    __syncthreads();

    // block tree: sum 4 regions in fp32, one atomic pass to g_S
    float* __restrict__ Sout = g_S[ssel];
    for (int t = tid; t < 320; t += 128) {
        float acc = s_priv[t] + s_priv[320 + t] + s_priv[640 + t] +
                    s_priv[960 + t];
        int bb  = t / 160;
        int rem = t - bb * 160;
        int o   = rem / 10;
        int jj  = rem - o * 10;
        atomicAdd(&Sout[(size_t)(b0 + bb) * JO_ + jj * 16 + o], acc);
    }
}

// ---------------------------------------------------------------------------
// v = squash(S * scale). mode 0: write g_V0. mode 1: g_VSUM = v + g_V0.
// mode 2: write dout (final output, [B,J,O,1] contiguous).
__global__ void k_squash(int ssel, float scale, int mode,
                         float* __restrict__ dout) {
    int i = blockIdx.x * blockDim.x + threadIdx.x;   // over B*J = 5120
    if (i >= B_ * J_) return;
    const float* s = g_S[ssel] + (size_t)i * O_;

    float sv[O_];
    float sq = 0.f;
    #pragma unroll
    for (int o = 0; o < O_; o++) {
        float t = s[o] * scale;
        sv[o] = t;
        sq += t * t;
    }
    float f = (sq / (1.0f + sq)) * rsqrtf(sq + 1e-8f);

    #pragma unroll
    for (int o = 0; o < O_; o++) {
        float vv = sv[o] * f;
        if (mode == 0)      g_V0[(size_t)i * O_ + o]   = vv;
        else if (mode == 1) g_VSUM[(size_t)i * O_ + o] = vv + g_V0[(size_t)i * O_ + o];
        else                dout[(size_t)i * O_ + o]   = vv;
    }
}

// ---------------------------------------------------------------------------
extern "C" void kernel_launch(void* const* d_in, const int* in_sizes, int n_in,
                              void* d_out, int out_size) {
    const float* x = (const float*)d_in[0];   // [512,1152,8]
    const float* W = (const float*)d_in[1];   // [1152,10,16,8]
    float* out = (float*)d_out;               // [512,10,16,1]
    (void)in_sizes; (void)n_in; (void)out_size;

    k_zero<<<240, 1024>>>();                          // zero S0,S1,S2
    k_uhat<<<2304, 128>>>(x, W);                      // u_hat(fp16) + sum_r -> S0
    k_squash<<<20, 256>>>(0, 1.0f / (float)J_, 0, nullptr);  // v0
    k_route<<<6144, 128>>>(0, 1);                     // iter 1 -> S1 (logits u.v0)
    k_squash<<<20, 256>>>(1, 1.0f, 1, nullptr);       // v1, VSUM = v0+v1
    k_route<<<6144, 128>>>(1, 2);                     // iter 2 -> S2 (logits u.(v0+v1))
    k_squash<<<20, 256>>>(2, 1.0f, 2, out);           // v2 -> output
}

// round 16
// speedup vs baseline: 1.1679x; 1.1679x over previous
#include <cuda_runtime.h>
#include <cuda_fp16.h>
#include <math.h>

#define B_  512
#define R_  1152
#define C_  8
#define J_  10
#define O_  16
#define JO_ 160

// Scratch (device globals: no allocations allowed in kernel_launch)
// u_hat stored fp16, packed across batch pairs: g_U16[p, r, jo] = (u[2p], u[2p+1])
__device__ __half2 g_U16[(size_t)(B_ / 2) * R_ * JO_];   // 188 MB
__device__ float   g_S[3][B_ * JO_];                     // s accumulators
__device__ float   g_V0[B_ * JO_];                       // v0
__device__ float   g_VSUM[B_ * JO_];                     // v0 + v1

__device__ __forceinline__ __half2 h2exp2_(__half2 x) {
    unsigned r, xi = *reinterpret_cast<unsigned*>(&x);
    asm("ex2.approx.f16x2 %0, %1;" : "=r"(r) : "r"(xi));
    return *reinterpret_cast<__half2*>(&r);
}

// ---------------------------------------------------------------------------
__global__ void k_zero() {
    int i = blockIdx.x * blockDim.x + threadIdx.x;
    if (i < 3 * B_ * JO_) ((float*)g_S)[i] = 0.0f;
}

// ---------------------------------------------------------------------------
// u_hat kernel — R12 version verbatim (proven 73us; R15's 128-thr variant
// was no faster). 256 threads, warp = (8 batches, 8-r slice), W staged in
// 40KB smem swizzled for conflict-free LDS.128.
__global__ void __launch_bounds__(256) k_uhat(const float* __restrict__ x,
                                              const float* __restrict__ W) {
    __shared__ float4 s_w[8 * 320];        // 8 r x 320 float4 = 40KB, swizzled
    const int tid  = threadIdx.x;
    const int lane = tid & 31;
    const int warp = tid >> 5;
    const int sl   = blockIdx.x % 144;     // 144 slices of 8 r
    const int bg   = blockIdx.x / 144;     // 8 groups of 64 b
    const int r0   = sl * 8;
    const int b0   = bg * 64 + warp * 8;   // this warp's 8 batches

    {
        const float4* Wg = (const float4*)(W + (size_t)r0 * 1280);
        for (int i = tid; i < 8 * 320; i += 256) {
            int r  = i / 320;
            int f  = i - r * 320;
            int jo = f >> 1, ch = f & 1;
            int k  = jo >> 5, l = jo & 31;
            s_w[r * 320 + (k * 2 + ch) * 32 + l] = Wg[r * 320 + f];
        }
    }
    __syncthreads();

    __half2 sacc2[4][5];
    #pragma unroll
    for (int pp = 0; pp < 4; pp++)
        #pragma unroll
        for (int k = 0; k < 5; k++) sacc2[pp][k] = __floats2half2_rn(0.f, 0.f);

    #pragma unroll
    for (int rq = 0; rq < 2; rq++) {
        const int rbase = r0 + rq * 4;

        float xq[8];
        #pragma unroll
        for (int bb = 0; bb < 8; bb++)
            xq[bb] = x[(size_t)(b0 + bb) * (R_ * C_) + (size_t)rbase * C_ + lane];

        #pragma unroll
        for (int rr = 0; rr < 4; rr++) {
            const int rloc = rq * 4 + rr;
            const int r    = rbase + rr;

            const float4* wrow = s_w + rloc * 320;
            float4 wa[5], wb[5];
            #pragma unroll
            for (int k = 0; k < 5; k++) {
                wa[k] = wrow[(2 * k)     * 32 + lane];
                wb[k] = wrow[(2 * k + 1) * 32 + lane];
            }

            float uhold[5];
            #pragma unroll
            for (int bb = 0; bb < 8; bb++) {
                float xc[8];
                #pragma unroll
                for (int c = 0; c < 8; c++)
                    xc[c] = __shfl_sync(0xffffffffu, xq[bb], rr * 8 + c);

                float u[5];
                #pragma unroll
                for (int k = 0; k < 5; k++) {
                    float t = wa[k].x * xc[0];
                    t = fmaf(wa[k].y, xc[1], t);
                    t = fmaf(wa[k].z, xc[2], t);
                    t = fmaf(wa[k].w, xc[3], t);
                    t = fmaf(wb[k].x, xc[4], t);
                    t = fmaf(wb[k].y, xc[5], t);
                    t = fmaf(wb[k].z, xc[6], t);
                    t = fmaf(wb[k].w, xc[7], t);
                    u[k] = t;
                }

                if (bb & 1) {
                    const int pp = bb >> 1;
                    __half2* up = g_U16 +
                        ((size_t)((b0 >> 1) + pp) * R_ + r) * JO_ + lane;
                    #pragma unroll
                    for (int k = 0; k < 5; k++) {
                        __half2 h = __floats2half2_rn(uhold[k], u[k]);
                        up[32 * k] = h;
                        sacc2[pp][k] = __hadd2(sacc2[pp][k], h);
                    }
                } else {
                    #pragma unroll
                    for (int k = 0; k < 5; k++) uhold[k] = u[k];
                }
            }
        }
    }

    #pragma unroll
    for (int pp = 0; pp < 4; pp++)
        #pragma unroll
        for (int k = 0; k < 5; k++) {
            float2 s = __half22float2(sacc2[pp][k]);
            int jo = lane + 32 * k;
            atomicAdd(&g_S[0][(b0 + 2 * pp)     * JO_ + jo], s.x);
            atomicAdd(&g_S[0][(b0 + 2 * pp + 1) * JO_ + jo], s.y);
        }
}

// ---------------------------------------------------------------------------
// Routing iteration v8 — R14's v6 body (v HOISTED in registers — R15 proved
// in-loop LDS for v is slower) with ONLY its resource leaks fixed:
//  - rr halves merged by one 16-SHFL pass -> s_priv 16 -> 4 regions
//    (smem 21KB -> 5KB, removes the smem occupancy cap).
//  - 128-thread blocks: at ~70 regs, 7 blocks x 4 warps = 28 warps/SM
//    (R14 had 24). No reg cap -> no spill risk.
// Math identical to R14: in-thread o-dot (4 LDG.128 + 16 HFMA2, no
// o-shuffles), softmax over j via 16-lane butterflies, fp16 fine (4-r
// windows) -> fp16 coarse -> fp32 smem epilogue, no hot-loop atomics.
__global__ void __launch_bounds__(128) k_route(int vsel, int ssel) {
    __shared__ float   s_priv[4 * 320];    // [warp][bb*160 + o*10 + j]
    __shared__ __half2 v_s[10 * 20];       // padded: v_s[j*20+o]
    const int tid  = threadIdx.x;
    const int lane = tid & 31;
    const int w    = tid >> 5;             // 0..3
    const int p    = blockIdx.x / 24;      // 256 pairs x 24 blocks
    const int g    = blockIdx.x - p * 24;
    const int slice = g * 4 + w;           // 0..95, 12 r each
    const int r0   = slice * 12;
    const int rr   = lane >> 4;
    const int j    = lane & 15;
    const bool act = (j < 10);
    const int jc   = act ? j : 0;          // clamped for unguarded smem reads
    const int b0   = 2 * p;

    const float* __restrict__ V = vsel ? g_VSUM : g_V0;
    const float LOG2E = 1.4426950408889634f;

    // stage v (block-uniform): v_s[j*20+o] = (V[b0,j,o], V[b1,j,o]) * log2e
    for (int t = tid; t < 160; t += 128) {
        int jj = t >> 4, oo = t & 15;
        v_s[jj * 20 + oo] = __floats2half2_rn(V[b0 * JO_ + t] * LOG2E,
                                              V[(b0 + 1) * JO_ + t] * LOG2E);
    }
    __syncthreads();

    // hoist v for this lane's j into 16 registers (R14 behavior — fast)
    __half2 vreg[16];
    {
        const uint4* vp4 = (const uint4*)(v_s + jc * 20);
        #pragma unroll
        for (int q = 0; q < 4; q++) {
            uint4 vq = vp4[q];
            vreg[q * 4 + 0] = *(__half2*)&vq.x;
            vreg[q * 4 + 1] = *(__half2*)&vq.y;
            vreg[q * 4 + 2] = *(__half2*)&vq.z;
            vreg[q * 4 + 3] = *(__half2*)&vq.w;
        }
    }

    const __half2 HZERO = __floats2half2_rn(0.f, 0.f);
    const __half2 NEG   = __floats2half2_rn(-60000.f, -60000.f);
    __half2 fine[16], coarse[16];
    #pragma unroll
    for (int o = 0; o < 16; o++) { fine[o] = HZERO; coarse[o] = HZERO; }

    const __half2* __restrict__ ubase =
        g_U16 + ((size_t)p * R_ + r0 + rr) * JO_ + jc * 16;

    #pragma unroll 2
    for (int step = 0; step < 6; step++) {
        // load u[r, j, 0..15] (b-paired half2) — 4x LDG.128, active lanes only
        __half2 u2[16];
        if (act) {
            const uint4* up4 =
                (const uint4*)(ubase + (size_t)(2 * step) * JO_);
            #pragma unroll
            for (int q = 0; q < 4; q++) {
                uint4 t = up4[q];
                u2[q * 4 + 0] = *(__half2*)&t.x;
                u2[q * 4 + 1] = *(__half2*)&t.y;
                u2[q * 4 + 2] = *(__half2*)&t.z;
                u2[q * 4 + 3] = *(__half2*)&t.w;
            }
        } else {
            #pragma unroll
            for (int o = 0; o < 16; o++) u2[o] = HZERO;
        }

        // in-thread dot over o (two chains for ILP), both batches per HFMA2
        __half2 aA = HZERO, aB = HZERO;
        #pragma unroll
        for (int q = 0; q < 4; q++) {
            aA = __hfma2(u2[q * 4 + 0], vreg[q * 4 + 0], aA);
            aB = __hfma2(u2[q * 4 + 1], vreg[q * 4 + 1], aB);
            aA = __hfma2(u2[q * 4 + 2], vreg[q * 4 + 2], aA);
            aB = __hfma2(u2[q * 4 + 3], vreg[q * 4 + 3], aB);
        }
        __half2 a2 = __hadd2(aA, aB);
        if (!act) a2 = NEG;                 // idle lanes neutral

        // softmax over j within each 16-lane half (4+4 SHFL total)
        __half2 m2 = a2;
        #pragma unroll
        for (int d = 1; d < 16; d <<= 1)
            m2 = __hmax2(m2, __shfl_xor_sync(0xffffffffu, m2, d));
        __half2 e2 = h2exp2_(__hsub2(a2, m2));
        __half2 z2 = e2;
        #pragma unroll
        for (int d = 1; d < 16; d <<= 1)
            z2 = __hadd2(z2, __shfl_xor_sync(0xffffffffu, z2, d));
        __half2 c2 = __hmul2(e2, h2rcp(z2));

        // accumulate c*u (idle lanes accumulate zeros — never stored)
        #pragma unroll
        for (int o = 0; o < 16; o++)
            fine[o] = __hfma2(c2, u2[o], fine[o]);

        if (step & 1) {                     // fold 4-r window into coarse
            #pragma unroll
            for (int o = 0; o < 16; o++) {
                coarse[o] = __hadd2(coarse[o], fine[o]);
                fine[o] = HZERO;
            }
        }
    }

    // merge rr halves: lanes (0,j) and (16,j) hold same (b,o,j) coordinates
    #pragma unroll
    for (int o = 0; o < 16; o++)
        coarse[o] = __hadd2(coarse[o],
                            __shfl_xor_sync(0xffffffffu, coarse[o], 16));

    // per-warp epilogue: one fp32 region per warp (plain STS, no atomics)
    if (act && rr == 0) {
        float* regn = s_priv + w * 320;
        #pragma unroll
        for (int o = 0; o < 16; o++) {
            float2 f = __half22float2(coarse[o]);
            regn[      o * 10 + j] = f.x;
            regn[160 + o * 10 + j] = f.y;
        }
    }
    __syncthreads();

    // block tree: sum 4 regions in fp32, one atomic pass to g_S
    float* __restrict__ Sout = g_S[ssel];
    for (int t = tid; t < 320; t += 128) {
        float acc = s_priv[t] + s_priv[320 + t] + s_priv[640 + t] +
                    s_priv[960 + t];
        int bb  = t / 160;
        int rem = t - bb * 160;
        int o   = rem / 10;
        int jj  = rem - o * 10;
        atomicAdd(&Sout[(size_t)(b0 + bb) * JO_ + jj * 16 + o], acc);
    }
}

// ---------------------------------------------------------------------------
// v = squash(S * scale). mode 0: write g_V0. mode 1: g_VSUM = v + g_V0.
// mode 2: write dout (final output, [B,J,O,1] contiguous).
__global__ void k_squash(int ssel, float scale, int mode,
                         float* __restrict__ dout) {
    int i = blockIdx.x * blockDim.x + threadIdx.x;   // over B*J = 5120
    if (i >= B_ * J_) return;
    const float* s = g_S[ssel] + (size_t)i * O_;

    float sv[O_];
    float sq = 0.f;
    #pragma unroll
    for (int o = 0; o < O_; o++) {
        float t = s[o] * scale;
        sv[o] = t;
        sq += t * t;
    }
    float f = (sq / (1.0f + sq)) * rsqrtf(sq + 1e-8f);

    #pragma unroll
    for (int o = 0; o < O_; o++) {
        float vv = sv[o] * f;
        if (mode == 0)      g_V0[(size_t)i * O_ + o]   = vv;
        else if (mode == 1) g_VSUM[(size_t)i * O_ + o] = vv + g_V0[(size_t)i * O_ + o];
        else                dout[(size_t)i * O_ + o]   = vv;
    }
}

// ---------------------------------------------------------------------------
extern "C" void kernel_launch(void* const* d_in, const int* in_sizes, int n_in,
                              void* d_out, int out_size) {
    const float* x = (const float*)d_in[0];   // [512,1152,8]
    const float* W = (const float*)d_in[1];   // [1152,10,16,8]
    float* out = (float*)d_out;               // [512,10,16,1]
    (void)in_sizes; (void)n_in; (void)out_size;

    k_zero<<<240, 1024>>>();                          // zero S0,S1,S2
    k_uhat<<<1152, 256>>>(x, W);                      // u_hat(fp16) + sum_r -> S0
    k_squash<<<20, 256>>>(0, 1.0f / (float)J_, 0, nullptr);  // v0
    k_route<<<6144, 128>>>(0, 1);                     // iter 1 -> S1 (logits u.v0)
    k_squash<<<20, 256>>>(1, 1.0f, 1, nullptr);       // v1, VSUM = v0+v1
    k_route<<<6144, 128>>>(1, 2);                     // iter 2 -> S2 (logits u.(v0+v1))
    k_squash<<<20, 256>>>(2, 1.0f, 2, out);           // v2 -> output
}

// round 17
// speedup vs baseline: 1.1685x; 1.0006x over previous
#include <cuda_runtime.h>
#include <cuda_fp16.h>
#include <math.h>

#define B_  512
#define R_  1152
#define C_  8
#define J_  10
#define O_  16
#define JO_ 160

// Scratch (device globals: no allocations allowed in kernel_launch)
// u_hat stored fp16, packed across batch pairs: g_U16[p, r, jo] = (u[2p], u[2p+1])
__device__ __half2 g_U16[(size_t)(B_ / 2) * R_ * JO_];   // 188 MB
__device__ float   g_S[3][B_ * JO_];                     // s accumulators
__device__ float   g_V0[B_ * JO_];                       // v0
__device__ float   g_VSUM[B_ * JO_];                     // v0 + v1

__device__ __forceinline__ __half2 h2exp2_(__half2 x) {
    unsigned r, xi = *reinterpret_cast<unsigned*>(&x);
    asm("ex2.approx.f16x2 %0, %1;" : "=r"(r) : "r"(xi));
    return *reinterpret_cast<__half2*>(&r);
}

// ---- packed fp32x2 helpers (sm_103a; FFMA2 only reachable via PTX) --------
typedef unsigned long long u64_;

__device__ __forceinline__ u64_ pack2_(float lo, float hi) {
    u64_ d;
    asm("mov.b64 %0, {%1, %2};" : "=l"(d) : "f"(lo), "f"(hi));
    return d;
}
__device__ __forceinline__ u64_ packdup_(float v) {
    u64_ d;
    asm("mov.b64 %0, {%1, %1};" : "=l"(d) : "f"(v));
    return d;
}
__device__ __forceinline__ void unpack2_(u64_ in, float& lo, float& hi) {
    asm("mov.b64 {%0, %1}, %2;" : "=f"(lo), "=f"(hi) : "l"(in));
}
__device__ __forceinline__ u64_ fma2_(u64_ a, u64_ b, u64_ c) {
    u64_ d;
    asm("fma.rn.f32x2 %0, %1, %2, %3;" : "=l"(d) : "l"(a), "l"(b), "l"(c));
    return d;
}
__device__ __forceinline__ u64_ mul2_(u64_ a, u64_ b) {
    u64_ d;
    asm("mul.rn.f32x2 %0, %1, %2;" : "=l"(d) : "l"(a), "l"(b));
    return d;
}
__device__ __forceinline__ u64_ add2_(u64_ a, u64_ b) {
    u64_ d;
    asm("add.rn.f32x2 %0, %1, %2;" : "=l"(d) : "l"(a), "l"(b));
    return d;
}

// ---------------------------------------------------------------------------
__global__ void k_zero() {
    int i = blockIdx.x * blockDim.x + threadIdx.x;
    if (i < 3 * B_ * JO_) ((float*)g_S)[i] = 0.0f;
}

// ---------------------------------------------------------------------------
// u_hat v9 — packed f32x2 math. k_uhat was measured AT the scalar-FFMA roof
// (23.6M warp-FFMA = 73us); fma.rn.f32x2 computes BOTH batches of a b-pair
// per instruction -> FMA-pipe work halves at full fp32 precision. W (w,w)
// duplicate packs ride the ALU pipe; x pairs ride 64-bit shuffles. Each warp
// owns 2 pairs (4 batches) x 8-r slice to keep registers under control;
// W staged in 40KB smem as before (conflict-free LDS.128).
__global__ void __launch_bounds__(256) k_uhat(const float* __restrict__ x,
                                              const float* __restrict__ W) {
    __shared__ float4 s_w[8 * 320];        // 8 r x 320 float4 = 40KB, swizzled
    const int tid  = threadIdx.x;
    const int lane = tid & 31;
    const int warp = tid >> 5;
    const int sl   = blockIdx.x % 144;     // 144 slices of 8 r
    const int bg   = blockIdx.x / 144;     // 16 groups of 32 b
    const int r0   = sl * 8;
    const int b0   = bg * 32 + warp * 4;   // this warp's 4 batches (2 pairs)
    const int p0   = b0 >> 1;

    {
        const float4* Wg = (const float4*)(W + (size_t)r0 * 1280);
        for (int i = tid; i < 8 * 320; i += 256) {
            int r  = i / 320;
            int f  = i - r * 320;
            int jo = f >> 1, ch = f & 1;
            int k  = jo >> 5, l = jo & 31;
            s_w[r * 320 + (k * 2 + ch) * 32 + l] = Wg[r * 320 + f];
        }
    }
    __syncthreads();

    __half2 sacc2[2][5];
    #pragma unroll
    for (int pp = 0; pp < 2; pp++)
        #pragma unroll
        for (int k = 0; k < 5; k++) sacc2[pp][k] = __floats2half2_rn(0.f, 0.f);

    #pragma unroll
    for (int rq = 0; rq < 2; rq++) {
        const int rbase = r0 + rq * 4;

        // x chunk: per b, 4 r x 8 c = 32 floats; pack batch pairs into f32x2
        float xq[4];
        #pragma unroll
        for (int bb = 0; bb < 4; bb++)
            xq[bb] = x[(size_t)(b0 + bb) * (R_ * C_) + (size_t)rbase * C_ + lane];
        u64_ xp[2] = { pack2_(xq[0], xq[1]), pack2_(xq[2], xq[3]) };

        #pragma unroll
        for (int rr = 0; rr < 4; rr++) {
            const int rloc = rq * 4 + rr;
            const int r    = rbase + rr;

            // broadcast x pairs for this r: xc2[pp][c] = (x[b0+2pp], x[b0+2pp+1])
            u64_ xc2[2][8];
            #pragma unroll
            for (int pp = 0; pp < 2; pp++)
                #pragma unroll
                for (int c = 0; c < 8; c++)
                    xc2[pp][c] = __shfl_sync(0xffffffffu, xp[pp], rr * 8 + c);

            const float4* wrow = s_w + rloc * 320;
            #pragma unroll
            for (int k = 0; k < 5; k++) {
                float4 wa = wrow[(2 * k)     * 32 + lane];
                float4 wb = wrow[(2 * k + 1) * 32 + lane];
                u64_ w2[8];
                w2[0] = packdup_(wa.x); w2[1] = packdup_(wa.y);
                w2[2] = packdup_(wa.z); w2[3] = packdup_(wa.w);
                w2[4] = packdup_(wb.x); w2[5] = packdup_(wb.y);
                w2[6] = packdup_(wb.z); w2[7] = packdup_(wb.w);

                #pragma unroll
                for (int pp = 0; pp < 2; pp++) {
                    // two FFMA2 chains for ILP, then one add
                    u64_ ea = mul2_(w2[0], xc2[pp][0]);
                    u64_ eb = mul2_(w2[1], xc2[pp][1]);
                    ea = fma2_(w2[2], xc2[pp][2], ea);
                    eb = fma2_(w2[3], xc2[pp][3], eb);
                    ea = fma2_(w2[4], xc2[pp][4], ea);
                    eb = fma2_(w2[5], xc2[pp][5], eb);
                    ea = fma2_(w2[6], xc2[pp][6], ea);
                    eb = fma2_(w2[7], xc2[pp][7], eb);
                    u64_ u2 = add2_(ea, eb);

                    float lo, hi;
                    unpack2_(u2, lo, hi);
                    __half2 h = __floats2half2_rn(lo, hi);   // (even b, odd b)
                    g_U16[((size_t)(p0 + pp) * R_ + r) * JO_ + lane + 32 * k] = h;
                    sacc2[pp][k] = __hadd2(sacc2[pp][k], h);
                }
            }
        }
    }

    // spread-address global atomics (20 per warp; proven fine)
    #pragma unroll
    for (int pp = 0; pp < 2; pp++)
        #pragma unroll
        for (int k = 0; k < 5; k++) {
            float2 s = __half22float2(sacc2[pp][k]);
            int jo = lane + 32 * k;
            atomicAdd(&g_S[0][(b0 + 2 * pp)     * JO_ + jo], s.x);
            atomicAdd(&g_S[0][(b0 + 2 * pp + 1) * JO_ + jo], s.y);
        }
}

// ---------------------------------------------------------------------------
// Routing iteration — R16 version UNCHANGED (46.7us measured best).
// In-thread o-dot (4 LDG.128 + 16 HFMA2, v hoisted in regs), softmax over j
// via 16-lane butterflies, fp16 fine (4-r windows) -> coarse, rr halves
// merged by one SHFL pass, fp32 smem epilogue, no hot-loop atomics.
__global__ void __launch_bounds__(128) k_route(int vsel, int ssel) {
    __shared__ float   s_priv[4 * 320];    // [warp][bb*160 + o*10 + j]
    __shared__ __half2 v_s[10 * 20];       // padded: v_s[j*20+o]
    const int tid  = threadIdx.x;
    const int lane = tid & 31;
    const int w    = tid >> 5;             // 0..3
    const int p    = blockIdx.x / 24;      // 256 pairs x 24 blocks
    const int g    = blockIdx.x - p * 24;
    const int slice = g * 4 + w;           // 0..95, 12 r each
    const int r0   = slice * 12;
    const int rr   = lane >> 4;
    const int j    = lane & 15;
    const bool act = (j < 10);
    const int jc   = act ? j : 0;          // clamped for unguarded smem reads
    const int b0   = 2 * p;

    const float* __restrict__ V = vsel ? g_VSUM : g_V0;
    const float LOG2E = 1.4426950408889634f;

    // stage v (block-uniform): v_s[j*20+o] = (V[b0,j,o], V[b1,j,o]) * log2e
    for (int t = tid; t < 160; t += 128) {
        int jj = t >> 4, oo = t & 15;
        v_s[jj * 20 + oo] = __floats2half2_rn(V[b0 * JO_ + t] * LOG2E,
                                              V[(b0 + 1) * JO_ + t] * LOG2E);
    }
    __syncthreads();

    // hoist v for this lane's j into 16 registers
    __half2 vreg[16];
    {
        const uint4* vp4 = (const uint4*)(v_s + jc * 20);
        #pragma unroll
        for (int q = 0; q < 4; q++) {
            uint4 vq = vp4[q];
            vreg[q * 4 + 0] = *(__half2*)&vq.x;
            vreg[q * 4 + 1] = *(__half2*)&vq.y;
            vreg[q * 4 + 2] = *(__half2*)&vq.z;
            vreg[q * 4 + 3] = *(__half2*)&vq.w;
        }
    }

    const __half2 HZERO = __floats2half2_rn(0.f, 0.f);
    const __half2 NEG   = __floats2half2_rn(-60000.f, -60000.f);
    __half2 fine[16], coarse[16];
    #pragma unroll
    for (int o = 0; o < 16; o++) { fine[o] = HZERO; coarse[o] = HZERO; }

    const __half2* __restrict__ ubase =
        g_U16 + ((size_t)p * R_ + r0 + rr) * JO_ + jc * 16;

    #pragma unroll 2
    for (int step = 0; step < 6; step++) {
        // load u[r, j, 0..15] (b-paired half2) — 4x LDG.128, active lanes only
        __half2 u2[16];
        if (act) {
            const uint4* up4 =
                (const uint4*)(ubase + (size_t)(2 * step) * JO_);
            #pragma unroll
            for (int q = 0; q < 4; q++) {
                uint4 t = up4[q];
                u2[q * 4 + 0] = *(__half2*)&t.x;
                u2[q * 4 + 1] = *(__half2*)&t.y;
                u2[q * 4 + 2] = *(__half2*)&t.z;
                u2[q * 4 + 3] = *(__half2*)&t.w;
            }
        } else {
            #pragma unroll
            for (int o = 0; o < 16; o++) u2[o] = HZERO;
        }

        // in-thread dot over o (two chains for ILP), both batches per HFMA2
        __half2 aA = HZERO, aB = HZERO;
        #pragma unroll
        for (int q = 0; q < 4; q++) {
            aA = __hfma2(u2[q * 4 + 0], vreg[q * 4 + 0], aA);
            aB = __hfma2(u2[q * 4 + 1], vreg[q * 4 + 1], aB);
            aA = __hfma2(u2[q * 4 + 2], vreg[q * 4 + 2], aA);
            aB = __hfma2(u2[q * 4 + 3], vreg[q * 4 + 3], aB);
        }
        __half2 a2 = __hadd2(aA, aB);
        if (!act) a2 = NEG;                 // idle lanes neutral

        // softmax over j within each 16-lane half (4+4 SHFL total)
        __half2 m2 = a2;
        #pragma unroll
        for (int d = 1; d < 16; d <<= 1)
            m2 = __hmax2(m2, __shfl_xor_sync(0xffffffffu, m2, d));
        __half2 e2 = h2exp2_(__hsub2(a2, m2));
        __half2 z2 = e2;
        #pragma unroll
        for (int d = 1; d < 16; d <<= 1)
            z2 = __hadd2(z2, __shfl_xor_sync(0xffffffffu, z2, d));
        __half2 c2 = __hmul2(e2, h2rcp(z2));

        // accumulate c*u (idle lanes accumulate zeros — never stored)
        #pragma unroll
        for (int o = 0; o < 16; o++)
            fine[o] = __hfma2(c2, u2[o], fine[o]);

        if (step & 1) {                     // fold 4-r window into coarse
            #pragma unroll
            for (int o = 0; o < 16; o++) {
                coarse[o] = __hadd2(coarse[o], fine[o]);
                fine[o] = HZERO;
            }
        }
    }

    // merge rr halves: lanes (0,j) and (16,j) hold same (b,o,j) coordinates
    #pragma unroll
    for (int o = 0; o < 16; o++)
        coarse[o] = __hadd2(coarse[o],
                            __shfl_xor_sync(0xffffffffu, coarse[o], 16));

    // per-warp epilogue: one fp32 region per warp (plain STS, no atomics)
    if (act && rr == 0) {
        float* regn = s_priv + w * 320;
        #pragma unroll
        for (int o = 0; o < 16; o++) {
            float2 f = __half22float2(coarse[o]);
            regn[      o * 10 + j] = f.x;
            regn[160 + o * 10 + j] = f.y;
        }
    }
    __syncthreads();

    // block tree: sum 4 regions in fp32, one atomic pass to g_S
    float* __restrict__ Sout = g_S[ssel];
    for (int t = tid; t < 320; t += 128) {
        float acc = s_priv[t] + s_priv[320 + t] + s_priv[640 + t] +
                    s_priv[960 + t];
        int bb  = t / 160;
        int rem = t - bb * 160;
        int o   = rem / 10;
        int jj  = rem - o * 10;
        atomicAdd(&Sout[(size_t)(b0 + bb) * JO_ + jj * 16 + o], acc);
    }
}

// ---------------------------------------------------------------------------
// v = squash(S * scale). mode 0: write g_V0. mode 1: g_VSUM = v + g_V0.
// mode 2: write dout (final output, [B,J,O,1] contiguous).
__global__ void k_squash(int ssel, float scale, int mode,
                         float* __restrict__ dout) {
    int i = blockIdx.x * blockDim.x + threadIdx.x;   // over B*J = 5120
    if (i >= B_ * J_) return;
    const float* s = g_S[ssel] + (size_t)i * O_;

    float sv[O_];
    float sq = 0.f;
    #pragma unroll
    for (int o = 0; o < O_; o++) {
        float t = s[o] * scale;
        sv[o] = t;
        sq += t * t;
    }
    float f = (sq / (1.0f + sq)) * rsqrtf(sq + 1e-8f);

    #pragma unroll
    for (int o = 0; o < O_; o++) {
        float vv = sv[o] * f;
        if (mode == 0)      g_V0[(size_t)i * O_ + o]   = vv;
        else if (mode == 1) g_VSUM[(size_t)i * O_ + o] = vv + g_V0[(size_t)i * O_ + o];
        else                dout[(size_t)i * O_ + o]   = vv;
    }
}

// ---------------------------------------------------------------------------
extern "C" void kernel_launch(void* const* d_in, const int* in_sizes, int n_in,
                              void* d_out, int out_size) {
    const float* x = (const float*)d_in[0];   // [512,1152,8]
    const float* W = (const float*)d_in[1];   // [1152,10,16,8]
    float* out = (float*)d_out;               // [512,10,16,1]
    (void)in_sizes; (void)n_in; (void)out_size;

    k_zero<<<240, 1024>>>();                          // zero S0,S1,S2
    k_uhat<<<2304, 256>>>(x, W);                      // u_hat(fp16) + sum_r -> S0
    k_squash<<<20, 256>>>(0, 1.0f / (float)J_, 0, nullptr);  // v0
    k_route<<<6144, 128>>>(0, 1);                     // iter 1 -> S1 (logits u.v0)
    k_squash<<<20, 256>>>(1, 1.0f, 1, nullptr);       // v1, VSUM = v0+v1
    k_route<<<6144, 128>>>(1, 2);                     // iter 2 -> S2 (logits u.(v0+v1))
    k_squash<<<20, 256>>>(2, 1.0f, 2, out);           // v2 -> output
}